// round 4
// baseline (speedup 1.0000x reference)
#include <cuda_runtime.h>

// Problem dims (fixed by reference)
#define B 16
#define S 4096
#define D 1024      // D_IN = H = D_OUT = 1024
#define NCHUNK 64
#define SCHUNK (S / NCHUNK)   // 64

// Scratch (no device allocs allowed)
__device__ float g_part[B * NCHUNK * D];   // 4 MB
__device__ float g_m[B * D];
__device__ float g_enc[B * D];

// K1: partial sums over an S-chunk. grid (NCHUNK, B), block 256.
// Each thread owns 4 contiguous floats (one float4 column) of D.
__global__ void reduce_partial_kernel(const float* __restrict__ x,
                                      float* __restrict__ part) {
    const int b = blockIdx.y;
    const int chunk = blockIdx.x;
    const int tid = threadIdx.x;  // 0..255

    const float4* xb = (const float4*)(x + (size_t)b * S * D + (size_t)chunk * SCHUNK * D);

    float4 acc0 = make_float4(0.f, 0.f, 0.f, 0.f);
    float4 acc1 = make_float4(0.f, 0.f, 0.f, 0.f);
    float4 acc2 = make_float4(0.f, 0.f, 0.f, 0.f);
    float4 acc3 = make_float4(0.f, 0.f, 0.f, 0.f);

    // SCHUNK = 64 rows, 4 independent accumulators -> MLP 4, no FADD chain bind
    #pragma unroll 4
    for (int s = 0; s < SCHUNK; s += 4) {
        float4 v0 = xb[(size_t)(s + 0) * (D / 4) + tid];
        float4 v1 = xb[(size_t)(s + 1) * (D / 4) + tid];
        float4 v2 = xb[(size_t)(s + 2) * (D / 4) + tid];
        float4 v3 = xb[(size_t)(s + 3) * (D / 4) + tid];
        acc0.x += v0.x; acc0.y += v0.y; acc0.z += v0.z; acc0.w += v0.w;
        acc1.x += v1.x; acc1.y += v1.y; acc1.z += v1.z; acc1.w += v1.w;
        acc2.x += v2.x; acc2.y += v2.y; acc2.z += v2.z; acc2.w += v2.w;
        acc3.x += v3.x; acc3.y += v3.y; acc3.z += v3.z; acc3.w += v3.w;
    }

    float4 acc;
    acc.x = (acc0.x + acc1.x) + (acc2.x + acc3.x);
    acc.y = (acc0.y + acc1.y) + (acc2.y + acc3.y);
    acc.z = (acc0.z + acc1.z) + (acc2.z + acc3.z);
    acc.w = (acc0.w + acc1.w) + (acc2.w + acc3.w);

    float4* p = (float4*)(part + ((size_t)b * NCHUNK + chunk) * D);
    p[tid] = acc;
}

// K2: combine NCHUNK partials, apply 1/S. One thread per (b,d).
__global__ void combine_kernel(const float* __restrict__ part,
                               float* __restrict__ m) {
    const int i = blockIdx.x * blockDim.x + threadIdx.x;  // 0 .. B*D-1
    if (i >= B * D) return;
    const int b = i >> 10;
    const int d = i & (D - 1);
    float s = 0.f;
    #pragma unroll
    for (int c = 0; c < NCHUNK; c++)
        s += part[((size_t)b * NCHUNK + c) * D + d];
    m[i] = s * (1.0f / (float)S);
}

// K3/K4: batch-fused GEMV. vout[b][n] = dot(vin[b], W[n]) + bias[n] for ALL b.
// grid = D/8 blocks, 8 warps/block, warp-per-output-row n.
// The full vin [B, D] (64 KB) is staged in dynamic smem; each warp loads its
// W row ONCE into registers and sweeps all 16 batch rows from smem.
__global__ void gemv_allb_kernel(const float* __restrict__ vin,   // [B, D]
                                 const float* __restrict__ W,     // [D, D]
                                 const float* __restrict__ bias,  // [D]
                                 float* __restrict__ vout) {      // [B, D]
    extern __shared__ float sh[];  // B * D floats = 64 KB

    // Cooperative fill: 4096 float4 over 256 threads -> 16 each, coalesced.
    for (int i = threadIdx.x; i < B * D / 4; i += 256)
        ((float4*)sh)[i] = ((const float4*)vin)[i];
    __syncthreads();

    const int warp = threadIdx.x >> 5;
    const int lane = threadIdx.x & 31;
    const int n = blockIdx.x * 8 + warp;

    // W row in registers: 8 x float4 per lane covers D=1024.
    const float4* Wr = (const float4*)(W + (size_t)n * D);
    float4 w[8];
    #pragma unroll
    for (int i = 0; i < 8; i++)
        w[i] = Wr[lane + 32 * i];

    float acc[B];
    #pragma unroll
    for (int b = 0; b < B; b++) acc[b] = 0.f;

    #pragma unroll
    for (int i = 0; i < 8; i++) {
        const int k4 = lane + 32 * i;
        #pragma unroll
        for (int b = 0; b < B; b++) {
            float4 v = ((const float4*)(sh + b * D))[k4];
            acc[b] += w[i].x * v.x + w[i].y * v.y + w[i].z * v.z + w[i].w * v.w;
        }
    }

    const float bn = bias[n];
    #pragma unroll
    for (int b = 0; b < B; b++) {
        float a = acc[b];
        #pragma unroll
        for (int o = 16; o; o >>= 1)
            a += __shfl_xor_sync(0xFFFFFFFFu, a, o);
        if (lane == 0)
            vout[(size_t)b * D + n] = a + bn;
    }
}

extern "C" void kernel_launch(void* const* d_in, const int* in_sizes, int n_in,
                              void* d_out, int out_size) {
    const float* x     = (const float*)d_in[0];
    const float* W_enc = (const float*)d_in[1];
    const float* b_enc = (const float*)d_in[2];
    const float* W_out = (const float*)d_in[3];
    const float* b_out = (const float*)d_in[4];
    float* out = (float*)d_out;

    float* part; cudaGetSymbolAddress((void**)&part, g_part);
    float* m;    cudaGetSymbolAddress((void**)&m,    g_m);
    float* enc;  cudaGetSymbolAddress((void**)&enc,  g_enc);

    const int smem = B * D * sizeof(float);  // 64 KB dynamic smem
    cudaFuncSetAttribute(gemv_allb_kernel,
                         cudaFuncAttributeMaxDynamicSharedMemorySize, smem);

    reduce_partial_kernel<<<dim3(NCHUNK, B), 256>>>(x, part);
    combine_kernel<<<(B * D + 255) / 256, 256>>>(part, m);
    gemv_allb_kernel<<<D / 8, 256, smem>>>(m,   W_enc, b_enc, enc);
    gemv_allb_kernel<<<D / 8, 256, smem>>>(enc, W_out, b_out, out);
}

// round 5
// speedup vs baseline: 1.1160x; 1.1160x over previous
#include <cuda_runtime.h>

// Problem dims (fixed by reference)
#define B 16
#define S 4096
#define D 1024      // D_IN = H = D_OUT = 1024
#define NCHUNK 64
#define SCHUNK (S / NCHUNK)   // 64
#define KSPLIT 4
#define KCHUNK (D / KSPLIT)   // 256

// Scratch (no device allocs allowed)
__device__ float g_part[B * NCHUNK * D];   // 4 MB
__device__ float g_m[B * D];
__device__ float g_enc[B * D];

// K1: partial sums over an S-chunk. grid (NCHUNK, B), block 256.
__global__ void reduce_partial_kernel(const float* __restrict__ x,
                                      float* __restrict__ part) {
    const int b = blockIdx.y;
    const int chunk = blockIdx.x;
    const int tid = threadIdx.x;  // 0..255

    const float4* xb = (const float4*)(x + (size_t)b * S * D + (size_t)chunk * SCHUNK * D);

    float4 acc0 = make_float4(0.f, 0.f, 0.f, 0.f);
    float4 acc1 = make_float4(0.f, 0.f, 0.f, 0.f);
    float4 acc2 = make_float4(0.f, 0.f, 0.f, 0.f);
    float4 acc3 = make_float4(0.f, 0.f, 0.f, 0.f);

    #pragma unroll 4
    for (int s = 0; s < SCHUNK; s += 4) {
        float4 v0 = xb[(size_t)(s + 0) * (D / 4) + tid];
        float4 v1 = xb[(size_t)(s + 1) * (D / 4) + tid];
        float4 v2 = xb[(size_t)(s + 2) * (D / 4) + tid];
        float4 v3 = xb[(size_t)(s + 3) * (D / 4) + tid];
        acc0.x += v0.x; acc0.y += v0.y; acc0.z += v0.z; acc0.w += v0.w;
        acc1.x += v1.x; acc1.y += v1.y; acc1.z += v1.z; acc1.w += v1.w;
        acc2.x += v2.x; acc2.y += v2.y; acc2.z += v2.z; acc2.w += v2.w;
        acc3.x += v3.x; acc3.y += v3.y; acc3.z += v3.z; acc3.w += v3.w;
    }

    float4 acc;
    acc.x = (acc0.x + acc1.x) + (acc2.x + acc3.x);
    acc.y = (acc0.y + acc1.y) + (acc2.y + acc3.y);
    acc.z = (acc0.z + acc1.z) + (acc2.z + acc3.z);
    acc.w = (acc0.w + acc1.w) + (acc2.w + acc3.w);

    float4* p = (float4*)(part + ((size_t)b * NCHUNK + chunk) * D);
    p[tid] = acc;
}

// K2: combine NCHUNK partials -> mean, AND pre-initialize both GEMV outputs
// with their biases (so the split-K gemv can atomicAdd partial dots into them).
__global__ void combine_kernel(const float* __restrict__ part,
                               float* __restrict__ m,
                               const float* __restrict__ b_enc,
                               float* __restrict__ enc,
                               const float* __restrict__ b_out,
                               float* __restrict__ out) {
    const int i = blockIdx.x * blockDim.x + threadIdx.x;  // 0 .. B*D-1
    if (i >= B * D) return;
    const int d = i & (D - 1);
    const int b = i >> 10;
    float s = 0.f;
    #pragma unroll
    for (int c = 0; c < NCHUNK; c++)
        s += part[((size_t)b * NCHUNK + c) * D + d];
    m[i] = s * (1.0f / (float)S);
    enc[i] = b_enc[d];
    out[i] = b_out[d];
}

// K3/K4: split-K batched GEMV. grid (D/8, KSPLIT), block 256 (8 warps).
// Warp w of block (bx, kc) computes, for n = bx*8+w, the partial dot of
// W[n][kc*256 : kc*256+256] against all 16 batch activations, then
// atomicAdds the 16 partials into vout (pre-initialized with bias).
// Activations (64 KB total) are L1/L2 resident; no smem, no syncs.
__global__ void gemv_split_kernel(const float* __restrict__ vin,   // [B, D]
                                  const float* __restrict__ W,     // [D, D]
                                  float* __restrict__ vout) {      // [B, D] (+= )
    const int warp = threadIdx.x >> 5;
    const int lane = threadIdx.x & 31;
    const int n = blockIdx.x * 8 + warp;
    const int K0 = blockIdx.y * KCHUNK;

    const float4* Wr = (const float4*)(W + (size_t)n * D + K0);
    const float4 w0 = Wr[lane];
    const float4 w1 = Wr[lane + 32];

    float acc[B];
    #pragma unroll
    for (int b = 0; b < B; b++) {
        const float4* vr = (const float4*)(vin + (size_t)b * D + K0);
        float4 v0 = vr[lane];
        float4 v1 = vr[lane + 32];
        acc[b] = ((w0.x * v0.x + w0.y * v0.y) + (w0.z * v0.z + w0.w * v0.w))
               + ((w1.x * v1.x + w1.y * v1.y) + (w1.z * v1.z + w1.w * v1.w));
    }

    // Butterfly-reduce all 16 accumulators across the warp.
    #pragma unroll
    for (int o = 16; o; o >>= 1) {
        #pragma unroll
        for (int b = 0; b < B; b++)
            acc[b] += __shfl_xor_sync(0xFFFFFFFFu, acc[b], o);
    }

    // Lanes 0..15 each commit one batch row's partial (static-index select).
    if (lane < B) {
        float v = acc[0];
        #pragma unroll
        for (int b = 1; b < B; b++)
            if (lane == b) v = acc[b];
        atomicAdd(&vout[(size_t)lane * D + n], v);
    }
}

extern "C" void kernel_launch(void* const* d_in, const int* in_sizes, int n_in,
                              void* d_out, int out_size) {
    const float* x     = (const float*)d_in[0];
    const float* W_enc = (const float*)d_in[1];
    const float* b_enc = (const float*)d_in[2];
    const float* W_out = (const float*)d_in[3];
    const float* b_out = (const float*)d_in[4];
    float* out = (float*)d_out;

    float* part; cudaGetSymbolAddress((void**)&part, g_part);
    float* m;    cudaGetSymbolAddress((void**)&m,    g_m);
    float* enc;  cudaGetSymbolAddress((void**)&enc,  g_enc);

    reduce_partial_kernel<<<dim3(NCHUNK, B), 256>>>(x, part);
    combine_kernel<<<(B * D + 255) / 256, 256>>>(part, m, b_enc, enc, b_out, out);
    gemv_split_kernel<<<dim3(D / 8, KSPLIT), 256>>>(m,   W_enc, enc);
    gemv_split_kernel<<<dim3(D / 8, KSPLIT), 256>>>(enc, W_out, out);
}

// round 6
// speedup vs baseline: 1.1241x; 1.0072x over previous
#include <cuda_runtime.h>

// Problem dims (fixed by reference)
#define B 16
#define S 4096
#define D 1024      // D_IN = H = D_OUT = 1024
#define NCHUNK 64
#define SCHUNK (S / NCHUNK)   // 64
#define KSPLIT 8
#define KCHUNK (D / KSPLIT)   // 128

// Scratch (no device allocs allowed)
__device__ float g_part[B * NCHUNK * D];   // 4 MB
__device__ float g_m[B * D];
__device__ float g_enc[B * D];

// K1: partial sums over an S-chunk. grid (NCHUNK, B), block 256.
__global__ void reduce_partial_kernel(const float* __restrict__ x,
                                      float* __restrict__ part) {
    const int b = blockIdx.y;
    const int chunk = blockIdx.x;
    const int tid = threadIdx.x;  // 0..255

    const float4* xb = (const float4*)(x + (size_t)b * S * D + (size_t)chunk * SCHUNK * D);

    float4 acc0 = make_float4(0.f, 0.f, 0.f, 0.f);
    float4 acc1 = make_float4(0.f, 0.f, 0.f, 0.f);
    float4 acc2 = make_float4(0.f, 0.f, 0.f, 0.f);
    float4 acc3 = make_float4(0.f, 0.f, 0.f, 0.f);

    #pragma unroll 4
    for (int s = 0; s < SCHUNK; s += 4) {
        float4 v0 = xb[(size_t)(s + 0) * (D / 4) + tid];
        float4 v1 = xb[(size_t)(s + 1) * (D / 4) + tid];
        float4 v2 = xb[(size_t)(s + 2) * (D / 4) + tid];
        float4 v3 = xb[(size_t)(s + 3) * (D / 4) + tid];
        acc0.x += v0.x; acc0.y += v0.y; acc0.z += v0.z; acc0.w += v0.w;
        acc1.x += v1.x; acc1.y += v1.y; acc1.z += v1.z; acc1.w += v1.w;
        acc2.x += v2.x; acc2.y += v2.y; acc2.z += v2.z; acc2.w += v2.w;
        acc3.x += v3.x; acc3.y += v3.y; acc3.z += v3.z; acc3.w += v3.w;
    }

    float4 acc;
    acc.x = (acc0.x + acc1.x) + (acc2.x + acc3.x);
    acc.y = (acc0.y + acc1.y) + (acc2.y + acc3.y);
    acc.z = (acc0.z + acc1.z) + (acc2.z + acc3.z);
    acc.w = (acc0.w + acc1.w) + (acc2.w + acc3.w);

    float4* p = (float4*)(part + ((size_t)b * NCHUNK + chunk) * D);
    p[tid] = acc;
}

// K2: combine NCHUNK partials -> mean, AND pre-initialize both GEMV outputs
// with their biases (so the split-K gemv can atomicAdd partial dots into them).
__global__ void combine_kernel(const float* __restrict__ part,
                               float* __restrict__ m,
                               const float* __restrict__ b_enc,
                               float* __restrict__ enc,
                               const float* __restrict__ b_out,
                               float* __restrict__ out) {
    const int i = blockIdx.x * blockDim.x + threadIdx.x;  // 0 .. B*D-1
    if (i >= B * D) return;
    const int d = i & (D - 1);
    const int b = i >> 10;
    float s = 0.f;
    #pragma unroll
    for (int c = 0; c < NCHUNK; c++)
        s += part[((size_t)b * NCHUNK + c) * D + d];
    m[i] = s * (1.0f / (float)S);
    enc[i] = b_enc[d];
    out[i] = b_out[d];
}

// K3/K4: split-K batched GEMV. grid (D/8, KSPLIT), block 256 (8 warps).
// Warp w of block (bx, kc): n = bx*8+w, computes partial dots of
// W[n][kc*128 : +128] against all 16 batch activations.
// Reduction: interleaved pairwise merge — 16 SHFLs total (vs 80 for
// per-b butterflies). Lane l ends holding the full warp sum for b = l&15.
__global__ void gemv_split_kernel(const float* __restrict__ vin,   // [B, D]
                                  const float* __restrict__ W,     // [D, D]
                                  float* __restrict__ vout) {      // [B, D] (+=)
    const int warp = threadIdx.x >> 5;
    const int lane = threadIdx.x & 31;
    const int n = blockIdx.x * 8 + warp;
    const int K0 = blockIdx.y * KCHUNK;

    const float4 w = ((const float4*)(W + (size_t)n * D + K0))[lane];

    float acc[B];
    #pragma unroll
    for (int b = 0; b < B; b++) {
        float4 v = ((const float4*)(vin + (size_t)b * D + K0))[lane];
        acc[b] = ((w.x * v.x + w.y * v.y) + (w.z * v.z + w.w * v.w));
    }

    // Stage 0 (bit 0 of b, xor 1): 16 -> 8 values, b-bit0 resolved to lane bit0.
    float u8[8];
    #pragma unroll
    for (int j = 0; j < 8; j++) {
        float mine  = (lane & 1) ? acc[2 * j + 1] : acc[2 * j];
        float other = (lane & 1) ? acc[2 * j]     : acc[2 * j + 1];
        u8[j] = mine + __shfl_xor_sync(0xFFFFFFFFu, other, 1);
    }
    // Stage 1 (bit 1, xor 2): 8 -> 4.
    float u4[4];
    #pragma unroll
    for (int j = 0; j < 4; j++) {
        float mine  = (lane & 2) ? u8[2 * j + 1] : u8[2 * j];
        float other = (lane & 2) ? u8[2 * j]     : u8[2 * j + 1];
        u4[j] = mine + __shfl_xor_sync(0xFFFFFFFFu, other, 2);
    }
    // Stage 2 (bit 2, xor 4): 4 -> 2.
    float u2[2];
    #pragma unroll
    for (int j = 0; j < 2; j++) {
        float mine  = (lane & 4) ? u4[2 * j + 1] : u4[2 * j];
        float other = (lane & 4) ? u4[2 * j]     : u4[2 * j + 1];
        u2[j] = mine + __shfl_xor_sync(0xFFFFFFFFu, other, 4);
    }
    // Stage 3 (bit 3, xor 8): 2 -> 1. Lane now holds b = lane & 15 (half-warp sum).
    float mine  = (lane & 8) ? u2[1] : u2[0];
    float other = (lane & 8) ? u2[0] : u2[1];
    float u = mine + __shfl_xor_sync(0xFFFFFFFFu, other, 8);
    // Stage 4: combine the two half-warps.
    u += __shfl_xor_sync(0xFFFFFFFFu, u, 16);

    if (lane < B)
        atomicAdd(&vout[(size_t)lane * D + n], u);
}

extern "C" void kernel_launch(void* const* d_in, const int* in_sizes, int n_in,
                              void* d_out, int out_size) {
    const float* x     = (const float*)d_in[0];
    const float* W_enc = (const float*)d_in[1];
    const float* b_enc = (const float*)d_in[2];
    const float* W_out = (const float*)d_in[3];
    const float* b_out = (const float*)d_in[4];
    float* out = (float*)d_out;

    float* part; cudaGetSymbolAddress((void**)&part, g_part);
    float* m;    cudaGetSymbolAddress((void**)&m,    g_m);
    float* enc;  cudaGetSymbolAddress((void**)&enc,  g_enc);

    reduce_partial_kernel<<<dim3(NCHUNK, B), 256>>>(x, part);
    combine_kernel<<<(B * D + 255) / 256, 256>>>(part, m, b_enc, enc, b_out, out);
    gemv_split_kernel<<<dim3(D / 8, KSPLIT), 256>>>(m,   W_enc, enc);
    gemv_split_kernel<<<dim3(D / 8, KSPLIT), 256>>>(enc, W_out, out);
}

// round 7
// speedup vs baseline: 1.1628x; 1.0345x over previous
#include <cuda_runtime.h>

// Problem dims (fixed by reference)
#define B 16
#define S 4096
#define D 1024      // D_IN = H = D_OUT = 1024
#define NCHUNK 64
#define SCHUNK (S / NCHUNK)   // 64
#define KSPLIT 8
#define KCHUNK (D / KSPLIT)   // 128

// Scratch (no device allocs allowed)
__device__ float g_part[B * NCHUNK * D];   // 4 MB
__device__ float g_m[B * D];
__device__ float g_enc[B * D];

// K1: partial sums over an S-chunk. grid (NCHUNK, B), block 256.
__global__ void reduce_partial_kernel(const float* __restrict__ x,
                                      float* __restrict__ part) {
    const int b = blockIdx.y;
    const int chunk = blockIdx.x;
    const int tid = threadIdx.x;  // 0..255

    const float4* xb = (const float4*)(x + (size_t)b * S * D + (size_t)chunk * SCHUNK * D);

    float4 acc0 = make_float4(0.f, 0.f, 0.f, 0.f);
    float4 acc1 = make_float4(0.f, 0.f, 0.f, 0.f);
    float4 acc2 = make_float4(0.f, 0.f, 0.f, 0.f);
    float4 acc3 = make_float4(0.f, 0.f, 0.f, 0.f);

    #pragma unroll 4
    for (int s = 0; s < SCHUNK; s += 4) {
        float4 v0 = xb[(size_t)(s + 0) * (D / 4) + tid];
        float4 v1 = xb[(size_t)(s + 1) * (D / 4) + tid];
        float4 v2 = xb[(size_t)(s + 2) * (D / 4) + tid];
        float4 v3 = xb[(size_t)(s + 3) * (D / 4) + tid];
        acc0.x += v0.x; acc0.y += v0.y; acc0.z += v0.z; acc0.w += v0.w;
        acc1.x += v1.x; acc1.y += v1.y; acc1.z += v1.z; acc1.w += v1.w;
        acc2.x += v2.x; acc2.y += v2.y; acc2.z += v2.z; acc2.w += v2.w;
        acc3.x += v3.x; acc3.y += v3.y; acc3.z += v3.z; acc3.w += v3.w;
    }

    float4 acc;
    acc.x = (acc0.x + acc1.x) + (acc2.x + acc3.x);
    acc.y = (acc0.y + acc1.y) + (acc2.y + acc3.y);
    acc.z = (acc0.z + acc1.z) + (acc2.z + acc3.z);
    acc.w = (acc0.w + acc1.w) + (acc2.w + acc3.w);

    float4* p = (float4*)(part + ((size_t)b * NCHUNK + chunk) * D);
    p[tid] = acc;
}

// K2: combine NCHUNK partials -> mean, AND pre-initialize both GEMV outputs
// with their biases (so the split-K gemv can atomicAdd partial dots into them).
__global__ void combine_kernel(const float* __restrict__ part,
                               float* __restrict__ m,
                               const float* __restrict__ b_enc,
                               float* __restrict__ enc,
                               const float* __restrict__ b_out,
                               float* __restrict__ out) {
    const int i = blockIdx.x * blockDim.x + threadIdx.x;  // 0 .. B*D-1
    if (i >= B * D) return;
    const int d = i & (D - 1);
    const int b = i >> 10;
    float s = 0.f;
    #pragma unroll
    for (int c = 0; c < NCHUNK; c++)
        s += part[((size_t)b * NCHUNK + c) * D + d];
    m[i] = s * (1.0f / (float)S);
    enc[i] = b_enc[d];
    out[i] = b_out[d];
}

// K3/K4: split-K batched GEMV with smem-staged activations.
// grid (D/8, KSPLIT), block 256 (8 warps). The block's vin K-tile
// (B x KCHUNK = 8 KB) is loaded into smem ONCE and shared by all 8 warps —
// this removes the 8x redundant L2 re-read that bound the previous version.
// Warp w: n = bx*8+w, partial dot of W[n][K0:K0+128] vs all 16 batch rows.
// Reduction: interleaved pairwise merge (16 SHFLs); lane l holds b = l&15.
__global__ void gemv_split_kernel(const float* __restrict__ vin,   // [B, D]
                                  const float* __restrict__ W,     // [D, D]
                                  float* __restrict__ vout) {      // [B, D] (+=)
    __shared__ float4 sh[B * (KCHUNK / 4)];   // 16 x 32 float4 = 8 KB

    const int K0 = blockIdx.y * KCHUNK;

    // Cooperative fill: 512 float4 over 256 threads, coalesced per row.
    {
        const int j = threadIdx.x & 31;           // float4 col within row
        const int b0 = threadIdx.x >> 5;          // 8 rows covered per pass
        const float4* v4 = (const float4*)vin;
        sh[b0 * 32 + j]       = v4[(size_t)b0 * (D / 4)       + K0 / 4 + j];
        sh[(b0 + 8) * 32 + j] = v4[(size_t)(b0 + 8) * (D / 4) + K0 / 4 + j];
    }
    __syncthreads();

    const int warp = threadIdx.x >> 5;
    const int lane = threadIdx.x & 31;
    const int n = blockIdx.x * 8 + warp;

    const float4 w = ((const float4*)(W + (size_t)n * D + K0))[lane];

    float acc[B];
    #pragma unroll
    for (int b = 0; b < B; b++) {
        float4 v = sh[b * 32 + lane];
        acc[b] = ((w.x * v.x + w.y * v.y) + (w.z * v.z + w.w * v.w));
    }

    // Stage 0 (bit 0 of b, xor 1): 16 -> 8.
    float u8[8];
    #pragma unroll
    for (int j = 0; j < 8; j++) {
        float mine  = (lane & 1) ? acc[2 * j + 1] : acc[2 * j];
        float other = (lane & 1) ? acc[2 * j]     : acc[2 * j + 1];
        u8[j] = mine + __shfl_xor_sync(0xFFFFFFFFu, other, 1);
    }
    // Stage 1 (bit 1, xor 2): 8 -> 4.
    float u4[4];
    #pragma unroll
    for (int j = 0; j < 4; j++) {
        float mine  = (lane & 2) ? u8[2 * j + 1] : u8[2 * j];
        float other = (lane & 2) ? u8[2 * j]     : u8[2 * j + 1];
        u4[j] = mine + __shfl_xor_sync(0xFFFFFFFFu, other, 2);
    }
    // Stage 2 (bit 2, xor 4): 4 -> 2.
    float u2[2];
    #pragma unroll
    for (int j = 0; j < 2; j++) {
        float mine  = (lane & 4) ? u4[2 * j + 1] : u4[2 * j];
        float other = (lane & 4) ? u4[2 * j]     : u4[2 * j + 1];
        u2[j] = mine + __shfl_xor_sync(0xFFFFFFFFu, other, 4);
    }
    // Stage 3 (bit 3, xor 8): 2 -> 1. Lane holds b = lane & 15 (half-warp sum).
    float mine  = (lane & 8) ? u2[1] : u2[0];
    float other = (lane & 8) ? u2[0] : u2[1];
    float u = mine + __shfl_xor_sync(0xFFFFFFFFu, other, 8);
    // Stage 4: combine the two half-warps.
    u += __shfl_xor_sync(0xFFFFFFFFu, u, 16);

    if (lane < B)
        atomicAdd(&vout[(size_t)lane * D + n], u);
}

extern "C" void kernel_launch(void* const* d_in, const int* in_sizes, int n_in,
                              void* d_out, int out_size) {
    const float* x     = (const float*)d_in[0];
    const float* W_enc = (const float*)d_in[1];
    const float* b_enc = (const float*)d_in[2];
    const float* W_out = (const float*)d_in[3];
    const float* b_out = (const float*)d_in[4];
    float* out = (float*)d_out;

    float* part; cudaGetSymbolAddress((void**)&part, g_part);
    float* m;    cudaGetSymbolAddress((void**)&m,    g_m);
    float* enc;  cudaGetSymbolAddress((void**)&enc,  g_enc);

    reduce_partial_kernel<<<dim3(NCHUNK, B), 256>>>(x, part);
    combine_kernel<<<(B * D + 255) / 256, 256>>>(part, m, b_enc, enc, b_out, out);
    gemv_split_kernel<<<dim3(D / 8, KSPLIT), 256>>>(m,   W_enc, enc);
    gemv_split_kernel<<<dim3(D / 8, KSPLIT), 256>>>(enc, W_out, out);
}

// round 8
// speedup vs baseline: 1.3064x; 1.1235x over previous
#include <cuda_runtime.h>

// Problem dims (fixed by reference)
#define B 16
#define S 4096
#define D 1024      // D_IN = H = D_OUT = 1024
#define NCHUNK 64
#define SCHUNK (S / NCHUNK)   // 64
#define KSPLIT 8
#define KCHUNK (D / KSPLIT)   // 128
#define R_GRID 512            // K1 blocks; each handles 2 of the 1024 tasks

// Scratch (no device allocs allowed)
__device__ float g_part[B * NCHUNK * D];   // 4 MB
__device__ float g_m[B * D];
__device__ float g_enc[B * D];

// K1: partial sums over S-chunks. grid R_GRID, block 256.
// 1024 (b,chunk) tasks; block t does tasks t and t+R_GRID (2 tasks each)
// to amortize the cross-CTA L1tex-queue spread and smooth the wave.
// x is read-once: use streaming loads (__ldcs) to avoid L2 pollution.
__global__ void reduce_partial_kernel(const float* __restrict__ x,
                                      float* __restrict__ part) {
    const int tid = threadIdx.x;  // 0..255

    #pragma unroll
    for (int t = 0; t < 2; t++) {
        const int task = blockIdx.x + t * R_GRID;   // 0..1023
        const int b = task >> 6;                    // task / NCHUNK
        const int chunk = task & (NCHUNK - 1);

        const float4* xb = (const float4*)(x + (size_t)b * S * D
                                             + (size_t)chunk * SCHUNK * D);

        float4 acc0 = make_float4(0.f, 0.f, 0.f, 0.f);
        float4 acc1 = make_float4(0.f, 0.f, 0.f, 0.f);
        float4 acc2 = make_float4(0.f, 0.f, 0.f, 0.f);
        float4 acc3 = make_float4(0.f, 0.f, 0.f, 0.f);

        #pragma unroll 4
        for (int s = 0; s < SCHUNK; s += 4) {
            float4 v0 = __ldcs(&xb[(size_t)(s + 0) * (D / 4) + tid]);
            float4 v1 = __ldcs(&xb[(size_t)(s + 1) * (D / 4) + tid]);
            float4 v2 = __ldcs(&xb[(size_t)(s + 2) * (D / 4) + tid]);
            float4 v3 = __ldcs(&xb[(size_t)(s + 3) * (D / 4) + tid]);
            acc0.x += v0.x; acc0.y += v0.y; acc0.z += v0.z; acc0.w += v0.w;
            acc1.x += v1.x; acc1.y += v1.y; acc1.z += v1.z; acc1.w += v1.w;
            acc2.x += v2.x; acc2.y += v2.y; acc2.z += v2.z; acc2.w += v2.w;
            acc3.x += v3.x; acc3.y += v3.y; acc3.z += v3.z; acc3.w += v3.w;
        }

        float4 acc;
        acc.x = (acc0.x + acc1.x) + (acc2.x + acc3.x);
        acc.y = (acc0.y + acc1.y) + (acc2.y + acc3.y);
        acc.z = (acc0.z + acc1.z) + (acc2.z + acc3.z);
        acc.w = (acc0.w + acc1.w) + (acc2.w + acc3.w);

        float4* p = (float4*)(part + ((size_t)b * NCHUNK + chunk) * D);
        p[tid] = acc;
    }
}

// K2: combine NCHUNK partials -> mean, AND pre-initialize both GEMV outputs
// with their biases (so the split-K gemv can atomicAdd partial dots into them).
__global__ void combine_kernel(const float* __restrict__ part,
                               float* __restrict__ m,
                               const float* __restrict__ b_enc,
                               float* __restrict__ enc,
                               const float* __restrict__ b_out,
                               float* __restrict__ out) {
    const int i = blockIdx.x * blockDim.x + threadIdx.x;  // 0 .. B*D-1
    if (i >= B * D) return;
    const int d = i & (D - 1);
    const int b = i >> 10;
    float s = 0.f;
    #pragma unroll
    for (int c = 0; c < NCHUNK; c++)
        s += part[((size_t)b * NCHUNK + c) * D + d];
    m[i] = s * (1.0f / (float)S);
    enc[i] = b_enc[d];
    out[i] = b_out[d];
}

// K3/K4: split-K batched GEMV with smem-staged activations.
// grid (D/8, KSPLIT), block 256 (8 warps). W row LDG is issued BEFORE the
// smem fill + barrier so its DRAM latency overlaps them (the block critical
// path was fill -> sync -> W-load -> compute, fully serialized).
__global__ void gemv_split_kernel(const float* __restrict__ vin,   // [B, D]
                                  const float* __restrict__ W,     // [D, D]
                                  float* __restrict__ vout) {      // [B, D] (+=)
    __shared__ float4 sh[B * (KCHUNK / 4)];   // 16 x 32 float4 = 8 KB

    const int K0 = blockIdx.y * KCHUNK;
    const int warp = threadIdx.x >> 5;
    const int lane = threadIdx.x & 31;
    const int n = blockIdx.x * 8 + warp;

    // Prefetch W row (no smem dependency) so it overlaps fill + sync.
    const float4 w = __ldg(&((const float4*)(W + (size_t)n * D + K0))[lane]);

    // Cooperative fill: 512 float4 over 256 threads, coalesced per row.
    {
        const int j = lane;                        // float4 col within row
        const int b0 = warp;                       // 8 rows covered per pass
        const float4* v4 = (const float4*)vin;
        sh[b0 * 32 + j]       = v4[(size_t)b0 * (D / 4)       + K0 / 4 + j];
        sh[(b0 + 8) * 32 + j] = v4[(size_t)(b0 + 8) * (D / 4) + K0 / 4 + j];
    }
    __syncthreads();

    float acc[B];
    #pragma unroll
    for (int b = 0; b < B; b++) {
        float4 v = sh[b * 32 + lane];
        acc[b] = ((w.x * v.x + w.y * v.y) + (w.z * v.z + w.w * v.w));
    }

    // Interleaved pairwise reduction: 16 SHFLs total.
    // Stage 0 (bit 0 of b, xor 1): 16 -> 8.
    float u8[8];
    #pragma unroll
    for (int j = 0; j < 8; j++) {
        float mine  = (lane & 1) ? acc[2 * j + 1] : acc[2 * j];
        float other = (lane & 1) ? acc[2 * j]     : acc[2 * j + 1];
        u8[j] = mine + __shfl_xor_sync(0xFFFFFFFFu, other, 1);
    }
    // Stage 1 (bit 1, xor 2): 8 -> 4.
    float u4[4];
    #pragma unroll
    for (int j = 0; j < 4; j++) {
        float mine  = (lane & 2) ? u8[2 * j + 1] : u8[2 * j];
        float other = (lane & 2) ? u8[2 * j]     : u8[2 * j + 1];
        u4[j] = mine + __shfl_xor_sync(0xFFFFFFFFu, other, 2);
    }
    // Stage 2 (bit 2, xor 4): 4 -> 2.
    float u2[2];
    #pragma unroll
    for (int j = 0; j < 2; j++) {
        float mine  = (lane & 4) ? u4[2 * j + 1] : u4[2 * j];
        float other = (lane & 4) ? u4[2 * j]     : u4[2 * j + 1];
        u2[j] = mine + __shfl_xor_sync(0xFFFFFFFFu, other, 4);
    }
    // Stage 3 (bit 3, xor 8): 2 -> 1. Lane holds b = lane & 15 (half-warp sum).
    float mine  = (lane & 8) ? u2[1] : u2[0];
    float other = (lane & 8) ? u2[0] : u2[1];
    float u = mine + __shfl_xor_sync(0xFFFFFFFFu, other, 8);
    // Stage 4: combine the two half-warps.
    u += __shfl_xor_sync(0xFFFFFFFFu, u, 16);

    if (lane < B)
        atomicAdd(&vout[(size_t)lane * D + n], u);
}

extern "C" void kernel_launch(void* const* d_in, const int* in_sizes, int n_in,
                              void* d_out, int out_size) {
    const float* x     = (const float*)d_in[0];
    const float* W_enc = (const float*)d_in[1];
    const float* b_enc = (const float*)d_in[2];
    const float* W_out = (const float*)d_in[3];
    const float* b_out = (const float*)d_in[4];
    float* out = (float*)d_out;

    float* part; cudaGetSymbolAddress((void**)&part, g_part);
    float* m;    cudaGetSymbolAddress((void**)&m,    g_m);
    float* enc;  cudaGetSymbolAddress((void**)&enc,  g_enc);

    reduce_partial_kernel<<<R_GRID, 256>>>(x, part);
    combine_kernel<<<(B * D + 255) / 256, 256>>>(part, m, b_enc, enc, b_out, out);
    gemv_split_kernel<<<dim3(D / 8, KSPLIT), 256>>>(m,   W_enc, enc);
    gemv_split_kernel<<<dim3(D / 8, KSPLIT), 256>>>(enc, W_out, out);
}